// round 11
// baseline (speedup 1.0000x reference)
#include <cuda_runtime.h>
#include <cuda_bf16.h>
#include <cstdint>
#include <math.h>

typedef unsigned int u32;

// Problem dims (fixed)
#define NB 64
#define TT 300
#define VV 25
#define SS 3

#define TC1 10
#define NCH1 (TT / TC1)          // 30 chunks for k1
#define TC3 10
#define NCH3 (TT / TC3)          // 30 chunks for k3

// Scratch (no allocations allowed)
__device__ float g_part[(size_t)NCH1 * NB * SS * VV * VV];  // 14.4 MB
__device__ float g_att[(size_t)NB * SS * VV * VV];          // 480 KB

// ---- bf16 mma helper -------------------------------------------------------
__device__ __forceinline__ void mma_bf16(float& d0, float& d1, float& d2, float& d3,
                                         u32 a0, u32 a1, u32 a2, u32 a3,
                                         u32 b0, u32 b1) {
    asm("mma.sync.aligned.m16n8k16.row.col.f32.bf16.bf16.f32 "
        "{%0,%1,%2,%3},{%4,%5,%6,%7},{%8,%9},{%0,%1,%2,%3};"
        : "+f"(d0), "+f"(d1), "+f"(d2), "+f"(d3)
        : "r"(a0), "r"(a1), "r"(a2), "r"(a3), "r"(b0), "r"(b1));
}
__device__ __forceinline__ u32 ldb2(const __nv_bfloat16* p) {
    return *reinterpret_cast<const u32*>(p);
}
// word-index swizzle for 16-word (32 bf16) rows: conflict-free frag loads
__device__ __forceinline__ int idx16(int r, int w) {
    return (r << 4) + (w ^ (((r >> 1) & 3) << 2));
}

// ============================================================================
// Kernel 1: conv_a/conv_b + score accumulation, all tensor cores. TC1=10.
// Phase 1: ab = W[96x64] @ Xt[256x64]^T (bf16). B-frags hoisted per warp.
// Phase 2: scores[s] = a_t @ b_t^T, K=160 exact (m = k*10+dt), stride 164.
// smem 111 KB -> 2 CTAs/SM @ 512 threads.
// ============================================================================
#define K1_ATS 164                        // a_t/b_t m-stride (bf16)
#define K1_SBLK (32 * K1_ATS)             // 5248 bf16 per subset
#define K1_OFF_XT 0                       // xt [256][72] bf16 = 9216 f
#define K1_OFF_WH 9216                    // wh [96][72] bf16  = 3456 f
#define K1_OFF_AT 12672                   // a_t [3][32][164] bf16 = 7872 f
#define K1_OFF_BT 20544
#define K1_NF     28416
#define K1_SMEM   (K1_NF * 4)             // 113664 B

__global__ __launch_bounds__(512, 2)
void k1_scores(const float* __restrict__ x, const float* __restrict__ wa,
               const float* __restrict__ ba, const float* __restrict__ wb,
               const float* __restrict__ bb)
{
    const int n = blockIdx.x, ch = blockIdx.y, t0 = ch * TC1;
    const int tid = threadIdx.x, lane = tid & 31, wrp = tid >> 5;  // 16 warps
    const int quad = lane >> 2, t4 = lane & 3;

    extern __shared__ float sm[];
    __nv_bfloat16* xt = (__nv_bfloat16*)(sm + K1_OFF_XT);   // [j][c] stride 72
    __nv_bfloat16* wh = (__nv_bfloat16*)(sm + K1_OFF_WH);   // [row][k] stride 72
    __nv_bfloat16* at = (__nv_bfloat16*)(sm + K1_OFF_AT);   // [s][v][m] stride 164
    __nv_bfloat16* bt = (__nv_bfloat16*)(sm + K1_OFF_BT);

    // stage weights (hi only) and x (bf16, transposed [j][c])
    for (int i = tid; i < 96 * 64; i += 512) {
        int row = i >> 6, k = i & 63;
        float v = (row < 48) ? wa[row * 64 + k] : wb[(row - 48) * 64 + k];
        wh[row * 72 + k] = __float2bfloat16_rn(v);
    }
    const float* xg = x + (size_t)n * 64 * 7500 + (size_t)t0 * 25;
    for (int i = tid; i < 64 * 256; i += 512) {
        int c = i >> 8, j = i & 255;
        float v = (j < 250) ? xg[(size_t)c * 7500 + j] : 0.f;
        xt[j * 72 + c] = __float2bfloat16_rn(v);
    }
    __syncthreads();

    // Phase 1: 96 jobs = 6 m-tiles x 16 n-tiles. Warp owns n-tile nq = wrp.
    {
        const int nq = wrp;
        // hoist B-frags for this column tile across all ks
        u32 B[4][2][2];
        #pragma unroll
        for (int ks = 0; ks < 4; ks++) {
            const int ka = ks * 16 + 2 * t4;
            #pragma unroll
            for (int h = 0; h < 2; h++) {
                int jc = nq * 16 + h * 8 + quad;
                B[ks][h][0] = ldb2(xt + jc * 72 + ka);
                B[ks][h][1] = ldb2(xt + jc * 72 + ka + 8);
            }
        }

        #pragma unroll
        for (int mi = 0; mi < 6; mi++) {
            const int r0 = mi * 16 + quad;
            float d[2][4];
            #pragma unroll
            for (int h = 0; h < 2; h++)
                #pragma unroll
                for (int q = 0; q < 4; q++) d[h][q] = 0.f;

            #pragma unroll
            for (int ks = 0; ks < 4; ks++) {
                const int ka = ks * 16 + 2 * t4;
                u32 a0 = ldb2(wh + r0 * 72 + ka);
                u32 a1 = ldb2(wh + (r0 + 8) * 72 + ka);
                u32 a2 = ldb2(wh + r0 * 72 + ka + 8);
                u32 a3 = ldb2(wh + (r0 + 8) * 72 + ka + 8);
                #pragma unroll
                for (int h = 0; h < 2; h++)
                    mma_bf16(d[h][0], d[h][1], d[h][2], d[h][3],
                             a0, a1, a2, a3, B[ks][h][0], B[ks][h][1]);
            }

            // epilogue: bias + bf16 scatter into a_t / b_t  (m = k*10+dt)
            const int ra = r0, rb = r0 + 8;
            const float biasA = (ra < 48) ? ba[ra] : bb[ra - 48];
            const float biasB = (rb < 48) ? ba[rb] : bb[rb - 48];
            #pragma unroll
            for (int h = 0; h < 2; h++) {
                #pragma unroll
                for (int cc = 0; cc < 2; cc++) {
                    int col = nq * 16 + h * 8 + 2 * t4 + cc;
                    if (col < 250) {
                        int dt = col / 25, v = col - dt * 25;
                        {
                            float val = d[h][cc] + biasA;
                            if (ra < 48)
                                at[(ra >> 4) * K1_SBLK + v * K1_ATS + (ra & 15) * 10 + dt] =
                                    __float2bfloat16_rn(val);
                            else {
                                int r2 = ra - 48;
                                bt[(r2 >> 4) * K1_SBLK + v * K1_ATS + (r2 & 15) * 10 + dt] =
                                    __float2bfloat16_rn(val);
                            }
                        }
                        {
                            float val = d[h][2 + cc] + biasB;
                            if (rb < 48)
                                at[(rb >> 4) * K1_SBLK + v * K1_ATS + (rb & 15) * 10 + dt] =
                                    __float2bfloat16_rn(val);
                            else {
                                int r2 = rb - 48;
                                bt[(r2 >> 4) * K1_SBLK + v * K1_ATS + (r2 & 15) * 10 + dt] =
                                    __float2bfloat16_rn(val);
                            }
                        }
                    }
                }
            }
        }
    }
    __syncthreads();

    // Phase 2: scores via mma. 24 jobs (3 s x 2 v-tiles x 4 u-tiles), K=160.
    const float inv = 1.0f / 4800.0f;
    for (int job = wrp; job < 24; job += 16) {
        const int s = job >> 3, r = job & 7, mt = r >> 2, nt = r & 3;
        const int v0 = mt * 16 + quad;
        const int u0 = nt * 8 + quad;
        const __nv_bfloat16* as_ = at + s * K1_SBLK;
        const __nv_bfloat16* bs_ = bt + s * K1_SBLK;

        float d0 = 0.f, d1 = 0.f, d2 = 0.f, d3 = 0.f;
        #pragma unroll
        for (int ks = 0; ks < 10; ks++) {
            const int me = 2 * t4 + 16 * ks;
            u32 a0 = ldb2(as_ + v0 * K1_ATS + me);
            u32 a1 = ldb2(as_ + (v0 + 8) * K1_ATS + me);
            u32 a2 = ldb2(as_ + v0 * K1_ATS + me + 8);
            u32 a3 = ldb2(as_ + (v0 + 8) * K1_ATS + me + 8);
            u32 b0 = ldb2(bs_ + u0 * K1_ATS + me);
            u32 b1 = ldb2(bs_ + u0 * K1_ATS + me + 8);
            mma_bf16(d0, d1, d2, d3, a0, a1, a2, a3, b0, b1);
        }

        float* dst = g_part + (((size_t)ch * NB + n) * SS + s) * 625;
        const int uA = nt * 8 + 2 * t4, uB = uA + 1;
        const int vA = v0, vB = v0 + 8;
        if (vA < 25) {
            if (uA < 25) dst[vA * 25 + uA] = d0 * inv;
            if (uB < 25) dst[vA * 25 + uB] = d1 * inv;
        }
        if (vB < 25) {
            if (uA < 25) dst[vB * 25 + uA] = d2 * inv;
            if (uB < 25) dst[vB * 25 + uB] = d3 * inv;
        }
    }
}

// ============================================================================
// Kernel 2: reduce chunk partials, softmax over v, add A+PA -> g_att
// ============================================================================
__global__ void k2_softmax(const float* __restrict__ A, const float* __restrict__ PA)
{
    const int n = blockIdx.x, s = blockIdx.y;
    __shared__ float sc[625];
    const int tid = threadIdx.x;

    for (int i = tid; i < 625; i += 256) {
        float acc = 0.f;
        for (int ch = 0; ch < NCH1; ch++)
            acc += g_part[(((size_t)ch * NB + n) * SS + s) * 625 + i];
        sc[i] = acc;
    }
    __syncthreads();

    if (tid < 25) {
        const int u = tid;
        float mx = -1e30f;
        #pragma unroll
        for (int v = 0; v < 25; v++) mx = fmaxf(mx, sc[v * 25 + u]);
        float e[25], sum = 0.f;
        #pragma unroll
        for (int v = 0; v < 25; v++) { e[v] = expf(sc[v * 25 + u] - mx); sum += e[v]; }
        const float rs = 1.f / sum;
        #pragma unroll
        for (int v = 0; v < 25; v++) {
            int idx = s * 625 + v * 25 + u;
            g_att[((size_t)n * SS + s) * 625 + v * 25 + u] = e[v] * rs + A[idx] + PA[idx];
        }
    }
}

// ============================================================================
// Kernel 3: phase Y and phase Z on tensor cores. TC3=10, 1024 thr, 1 CTA/SM.
// Phase Y: D[m=(c,dt)][u] = X[640x32] @ attT (3-term hi/lo split).
// Phase Z: z += wd_s @ y_s (3-term), y [256][72] hi/lo bf16.
// smem ~183 KB.
// ============================================================================
#define K3_OFF_XTH 0                      // [640][16w] = 10240 f
#define K3_OFF_XTL 10240
#define K3_OFF_ATH 20480                  // [3][32][16w] = 1536 f
#define K3_OFF_ATL 22016
#define K3_OFF_YH  23552                  // [256][72] bf16 = 9216 f
#define K3_OFF_YL  32768
#define K3_OFF_WH  41984                  // [64][72] bf16 = 2304 f
#define K3_OFF_WL  44288
#define K3_OFF_SC  46592
#define K3_OFF_SH  46656
#define K3_NF      46720
#define K3_SMEM    (K3_NF * 4)            // 186880 B

__global__ __launch_bounds__(1024, 1)
void k3_fused(const float* __restrict__ x, const float* __restrict__ wd,
              const float* __restrict__ bd,
              const float* __restrict__ gma, const float* __restrict__ bta,
              const float* __restrict__ mu,  const float* __restrict__ var,
              float* __restrict__ out)
{
    const int n = blockIdx.x, ch = blockIdx.y, t0 = ch * TC3;
    const int tid = threadIdx.x, lane = tid & 31, wrp = tid >> 5;  // 32 warps
    const int quad = lane >> 2, t4 = lane & 3;

    extern __shared__ float sm[];
    u32* xthw = (u32*)(sm + K3_OFF_XTH);   // [640][16 words] swizzled
    u32* xtlw = (u32*)(sm + K3_OFF_XTL);
    u32* athw = (u32*)(sm + K3_OFF_ATH);   // [3][32][16 words] swizzled
    u32* atlw = (u32*)(sm + K3_OFF_ATL);
    __nv_bfloat16* xth_b = (__nv_bfloat16*)(sm + K3_OFF_XTH);
    __nv_bfloat16* xtl_b = (__nv_bfloat16*)(sm + K3_OFF_XTL);
    __nv_bfloat16* y_hi = (__nv_bfloat16*)(sm + K3_OFF_YH);  // [256][72]
    __nv_bfloat16* y_lo = (__nv_bfloat16*)(sm + K3_OFF_YL);
    __nv_bfloat16* w_hi = (__nv_bfloat16*)(sm + K3_OFF_WH);  // [64][72]
    __nv_bfloat16* w_lo = (__nv_bfloat16*)(sm + K3_OFF_WL);
    float* sc_sm = sm + K3_OFF_SC;
    float* sh_sm = sm + K3_OFF_SH;

    // ---- stage x as hi/lo bf16 pairs, [m=(c*10+dt)][v], swizzled -----------
    const float* xg = x + (size_t)n * 64 * 7500 + (size_t)t0 * 25;
    for (int i = tid; i < 640 * 16; i += 1024) {
        int m = i >> 4, w = i & 15;
        int c = m / 10, dt = m - 10 * c;
        int v0 = 2 * w;
        float f0 = (v0 < 25)     ? xg[(size_t)c * 7500 + dt * 25 + v0]     : 0.f;
        float f1 = (v0 + 1 < 25) ? xg[(size_t)c * 7500 + dt * 25 + v0 + 1] : 0.f;
        __nv_bfloat16 h0 = __float2bfloat16_rn(f0);
        __nv_bfloat16 h1 = __float2bfloat16_rn(f1);
        __nv_bfloat16 l0 = __float2bfloat16_rn(f0 - __bfloat162float(h0));
        __nv_bfloat16 l1 = __float2bfloat16_rn(f1 - __bfloat162float(h1));
        int a = idx16(m, w);
        xthw[a] = ((u32)*(unsigned short*)&h1 << 16) | *(unsigned short*)&h0;
        xtlw[a] = ((u32)*(unsigned short*)&l1 << 16) | *(unsigned short*)&l0;
    }
    // ---- stage att transposed [s][u][v], hi/lo, swizzled -------------------
    for (int i = tid; i < 3 * 512; i += 1024) {
        int s = i >> 9, rem = i & 511;
        int u = rem >> 4, w = rem & 15;
        int v0 = 2 * w;
        const float* ag = g_att + ((size_t)n * SS + s) * 625;
        float f0 = (u < 25 && v0 < 25)     ? ag[v0 * 25 + u]       : 0.f;
        float f1 = (u < 25 && v0 + 1 < 25) ? ag[(v0 + 1) * 25 + u] : 0.f;
        __nv_bfloat16 h0 = __float2bfloat16_rn(f0);
        __nv_bfloat16 h1 = __float2bfloat16_rn(f1);
        __nv_bfloat16 l0 = __float2bfloat16_rn(f0 - __bfloat162float(h0));
        __nv_bfloat16 l1 = __float2bfloat16_rn(f1 - __bfloat162float(h1));
        int a = s * 512 + idx16(u, w);
        athw[a] = ((u32)*(unsigned short*)&h1 << 16) | *(unsigned short*)&h0;
        atlw[a] = ((u32)*(unsigned short*)&l1 << 16) | *(unsigned short*)&l0;
    }
    if (tid < 64) {
        float scl = gma[tid] * rsqrtf(var[tid] + 1e-5f);
        float bsum = bd[tid] + bd[64 + tid] + bd[128 + tid];
        sc_sm[tid] = scl;
        sh_sm[tid] = (bsum - mu[tid]) * scl + bta[tid];
    }
    if (tid < 6 * 72) {  // zero y rows j=250..255 (N-padding for phase Z)
        int j = 250 + tid / 72, cidx = tid % 72;
        y_hi[j * 72 + cidx] = __float2bfloat16_rn(0.f);
        y_lo[j * 72 + cidx] = __float2bfloat16_rn(0.f);
    }

    // warp tiles: phase Y (mgY 0..7, ntY 0..3); phase Z (otZ 0..3, jgZ 0..7)
    const int mgY = wrp >> 2, ntY = wrp & 3;
    const int otZ = wrp >> 3, jgZ = wrp & 7;
    const int o0 = otZ * 16;
    float dz[4][4];
    #pragma unroll
    for (int f = 0; f < 4; f++)
        #pragma unroll
        for (int q = 0; q < 4; q++) dz[f][q] = 0.f;

    for (int s = 0; s < SS; s++) {
        __syncthreads();   // prev phase Z done with w/y; covers init on s=0

        // stage this subset's conv_d weights hi/lo (stride 72)
        for (int i = tid; i < 4096; i += 1024) {
            int o = i >> 6, k = i & 63;
            float v = wd[(size_t)s * 4096 + i];
            __nv_bfloat16 h = __float2bfloat16_rn(v);
            w_hi[o * 72 + k] = h;
            w_lo[o * 72 + k] = __float2bfloat16_rn(v - __bfloat162float(h));
        }

        // ---- Phase Y (tensor cores): D[m][u] over K=v=32 -------------------
        {
            const int u = ntY * 8 + quad;
            u32 bh[2][2], bl[2][2];
            #pragma unroll
            for (int ks = 0; ks < 2; ks++) {
                bh[ks][0] = athw[s * 512 + idx16(u, t4 + 8 * ks)];
                bh[ks][1] = athw[s * 512 + idx16(u, t4 + 4 + 8 * ks)];
                bl[ks][0] = atlw[s * 512 + idx16(u, t4 + 8 * ks)];
                bl[ks][1] = atlw[s * 512 + idx16(u, t4 + 4 + 8 * ks)];
            }
            #pragma unroll
            for (int q = 0; q < 5; q++) {
                const int mt = mgY * 5 + q;
                const int m0 = mt * 16 + quad, m1 = m0 + 8;
                float D0 = 0.f, D1 = 0.f, D2 = 0.f, D3 = 0.f;
                #pragma unroll
                for (int ks = 0; ks < 2; ks++) {
                    u32 ah0 = xthw[idx16(m0, t4 + 8 * ks)];
                    u32 ah1 = xthw[idx16(m1, t4 + 8 * ks)];
                    u32 ah2 = xthw[idx16(m0, t4 + 4 + 8 * ks)];
                    u32 ah3 = xthw[idx16(m1, t4 + 4 + 8 * ks)];
                    u32 al0 = xtlw[idx16(m0, t4 + 8 * ks)];
                    u32 al1 = xtlw[idx16(m1, t4 + 8 * ks)];
                    u32 al2 = xtlw[idx16(m0, t4 + 4 + 8 * ks)];
                    u32 al3 = xtlw[idx16(m1, t4 + 4 + 8 * ks)];
                    mma_bf16(D0, D1, D2, D3, ah0, ah1, ah2, ah3, bh[ks][0], bh[ks][1]);
                    mma_bf16(D0, D1, D2, D3, ah0, ah1, ah2, ah3, bl[ks][0], bl[ks][1]);
                    mma_bf16(D0, D1, D2, D3, al0, al1, al2, al3, bh[ks][0], bh[ks][1]);
                }
                // scatter y hi/lo: (m, u) -> y[j = dt*25+u][c]
                const int u0 = ntY * 8 + 2 * t4;
                #pragma unroll
                for (int cc = 0; cc < 2; cc++) {
                    int uu = u0 + cc;
                    if (uu < 25) {
                        {
                            int c = m0 / 10, dt = m0 - 10 * c;
                            int j = dt * 25 + uu;
                            float val = cc ? D1 : D0;
                            __nv_bfloat16 h = __float2bfloat16_rn(val);
                            y_hi[j * 72 + c] = h;
                            y_lo[j * 72 + c] = __float2bfloat16_rn(val - __bfloat162float(h));
                        }
                        {
                            int c = m1 / 10, dt = m1 - 10 * c;
                            int j = dt * 25 + uu;
                            float val = cc ? D3 : D2;
                            __nv_bfloat16 h = __float2bfloat16_rn(val);
                            y_hi[j * 72 + c] = h;
                            y_lo[j * 72 + c] = __float2bfloat16_rn(val - __bfloat162float(h));
                        }
                    }
                }
            }
        }
        __syncthreads();

        // ---- Phase Z (tensor cores): z += wd_s @ y_s, K=64 -----------------
        #pragma unroll
        for (int k0 = 0; k0 < 64; k0 += 16) {
            const int ar0 = (o0 + quad) * 72 + k0 + 2 * t4;
            const int ar1 = (o0 + quad + 8) * 72 + k0 + 2 * t4;
            u32 ah0 = ldb2(w_hi + ar0),     ah1 = ldb2(w_hi + ar1);
            u32 ah2 = ldb2(w_hi + ar0 + 8), ah3 = ldb2(w_hi + ar1 + 8);
            u32 al0 = ldb2(w_lo + ar0),     al1 = ldb2(w_lo + ar1);
            u32 al2 = ldb2(w_lo + ar0 + 8), al3 = ldb2(w_lo + ar1 + 8);
            #pragma unroll
            for (int f = 0; f < 4; f++) {
                int j = jgZ * 32 + f * 8 + quad;
                int br = j * 72 + k0 + 2 * t4;
                u32 bh0 = ldb2(y_hi + br), bh1 = ldb2(y_hi + br + 8);
                u32 bl0 = ldb2(y_lo + br), bl1 = ldb2(y_lo + br + 8);
                mma_bf16(dz[f][0], dz[f][1], dz[f][2], dz[f][3],
                         ah0, ah1, ah2, ah3, bh0, bh1);
                mma_bf16(dz[f][0], dz[f][1], dz[f][2], dz[f][3],
                         ah0, ah1, ah2, ah3, bl0, bl1);
                mma_bf16(dz[f][0], dz[f][1], dz[f][2], dz[f][3],
                         al0, al1, al2, al3, bh0, bh1);
            }
        }
    }

    // ---- epilogue: BN + residual (x = hi+lo) + ReLU ------------------------
    float* og = out + (size_t)n * 64 * 7500 + (size_t)t0 * 25;
    #pragma unroll
    for (int f = 0; f < 4; f++) {
        int jb = jgZ * 32 + f * 8 + 2 * t4;
        #pragma unroll
        for (int h = 0; h < 2; h++) {
            int o = o0 + quad + 8 * h;
            float scl = sc_sm[o], shf = sh_sm[o];
            #pragma unroll
            for (int cc = 0; cc < 2; cc++) {
                int j = jb + cc;
                if (j < 250) {
                    int dt = j / 25, u = j - dt * 25;
                    int m = o * 10 + dt;
                    int ew = 2 * idx16(m, u >> 1) + (u & 1);
                    float xv = __bfloat162float(xth_b[ew]) + __bfloat162float(xtl_b[ew]);
                    float r = fmaf(dz[f][2 * h + cc], scl, shf) + xv;
                    og[(size_t)o * 7500 + j] = fmaxf(r, 0.f);
                }
            }
        }
    }
}

// ============================================================================
extern "C" void kernel_launch(void* const* d_in, const int* in_sizes, int n_in,
                              void* d_out, int out_size)
{
    const float* x   = (const float*)d_in[0];
    const float* A   = (const float*)d_in[1];
    const float* PA  = (const float*)d_in[2];
    const float* wa  = (const float*)d_in[3];
    const float* ba  = (const float*)d_in[4];
    const float* wb  = (const float*)d_in[5];
    const float* bb  = (const float*)d_in[6];
    const float* wd  = (const float*)d_in[7];
    const float* bd  = (const float*)d_in[8];
    const float* gma = (const float*)d_in[9];
    const float* bta = (const float*)d_in[10];
    const float* mu  = (const float*)d_in[11];
    const float* var = (const float*)d_in[12];
    float* out = (float*)d_out;

    cudaFuncSetAttribute(k1_scores, cudaFuncAttributeMaxDynamicSharedMemorySize, K1_SMEM);
    cudaFuncSetAttribute(k3_fused,  cudaFuncAttributeMaxDynamicSharedMemorySize, K3_SMEM);

    k1_scores<<<dim3(NB, NCH1), 512, K1_SMEM>>>(x, wa, ba, wb, bb);
    k2_softmax<<<dim3(NB, SS), 256>>>(A, PA);
    k3_fused<<<dim3(NB, NCH3), 1024, K3_SMEM>>>(x, wd, bd, gma, bta, mu, var, out);
}

// round 12
// speedup vs baseline: 1.2020x; 1.2020x over previous
#include <cuda_runtime.h>
#include <cuda_bf16.h>
#include <cstdint>
#include <math.h>

typedef unsigned int u32;

// Problem dims (fixed)
#define NB 64
#define TT 300
#define VV 25
#define SS 3

#define TC1 10
#define NCH1 (TT / TC1)          // 30 chunks for k1
#define TC3 5
#define NCH3 (TT / TC3)          // 60 chunks for k3

// Scratch (no allocations allowed)
__device__ float g_part[(size_t)NCH1 * NB * SS * VV * VV];  // 14.4 MB
__device__ float g_att[(size_t)NB * SS * VV * VV];          // 480 KB

// ---- bf16 mma helper -------------------------------------------------------
__device__ __forceinline__ void mma_bf16(float& d0, float& d1, float& d2, float& d3,
                                         u32 a0, u32 a1, u32 a2, u32 a3,
                                         u32 b0, u32 b1) {
    asm("mma.sync.aligned.m16n8k16.row.col.f32.bf16.bf16.f32 "
        "{%0,%1,%2,%3},{%4,%5,%6,%7},{%8,%9},{%0,%1,%2,%3};"
        : "+f"(d0), "+f"(d1), "+f"(d2), "+f"(d3)
        : "r"(a0), "r"(a1), "r"(a2), "r"(a3), "r"(b0), "r"(b1));
}
__device__ __forceinline__ u32 ldb2(const __nv_bfloat16* p) {
    return *reinterpret_cast<const u32*>(p);
}
// word-index swizzle for 16-word (32 bf16) rows: conflict-free frag loads
__device__ __forceinline__ int idx16(int r, int w) {
    return (r << 4) + (w ^ (((r >> 1) & 3) << 2));
}

// ============================================================================
// Kernel 1: conv_a/conv_b + score accumulation, all tensor cores. TC1=10.
// (R11 version — measured 103 us)
// ============================================================================
#define K1_ATS 164                        // a_t/b_t m-stride (bf16)
#define K1_SBLK (32 * K1_ATS)             // 5248 bf16 per subset
#define K1_OFF_XT 0                       // xt [256][72] bf16 = 9216 f
#define K1_OFF_WH 9216                    // wh [96][72] bf16  = 3456 f
#define K1_OFF_AT 12672                   // a_t [3][32][164] bf16 = 7872 f
#define K1_OFF_BT 20544
#define K1_NF     28416
#define K1_SMEM   (K1_NF * 4)             // 113664 B

__global__ __launch_bounds__(512, 2)
void k1_scores(const float* __restrict__ x, const float* __restrict__ wa,
               const float* __restrict__ ba, const float* __restrict__ wb,
               const float* __restrict__ bb)
{
    const int n = blockIdx.x, ch = blockIdx.y, t0 = ch * TC1;
    const int tid = threadIdx.x, lane = tid & 31, wrp = tid >> 5;  // 16 warps
    const int quad = lane >> 2, t4 = lane & 3;

    extern __shared__ float sm[];
    __nv_bfloat16* xt = (__nv_bfloat16*)(sm + K1_OFF_XT);   // [j][c] stride 72
    __nv_bfloat16* wh = (__nv_bfloat16*)(sm + K1_OFF_WH);   // [row][k] stride 72
    __nv_bfloat16* at = (__nv_bfloat16*)(sm + K1_OFF_AT);   // [s][v][m] stride 164
    __nv_bfloat16* bt = (__nv_bfloat16*)(sm + K1_OFF_BT);

    for (int i = tid; i < 96 * 64; i += 512) {
        int row = i >> 6, k = i & 63;
        float v = (row < 48) ? wa[row * 64 + k] : wb[(row - 48) * 64 + k];
        wh[row * 72 + k] = __float2bfloat16_rn(v);
    }
    const float* xg = x + (size_t)n * 64 * 7500 + (size_t)t0 * 25;
    for (int i = tid; i < 64 * 256; i += 512) {
        int c = i >> 8, j = i & 255;
        float v = (j < 250) ? xg[(size_t)c * 7500 + j] : 0.f;
        xt[j * 72 + c] = __float2bfloat16_rn(v);
    }
    __syncthreads();

    // Phase 1: 96 jobs = 6 m-tiles x 16 n-tiles. Warp owns n-tile nq = wrp.
    {
        const int nq = wrp;
        u32 B[4][2][2];
        #pragma unroll
        for (int ks = 0; ks < 4; ks++) {
            const int ka = ks * 16 + 2 * t4;
            #pragma unroll
            for (int h = 0; h < 2; h++) {
                int jc = nq * 16 + h * 8 + quad;
                B[ks][h][0] = ldb2(xt + jc * 72 + ka);
                B[ks][h][1] = ldb2(xt + jc * 72 + ka + 8);
            }
        }

        #pragma unroll
        for (int mi = 0; mi < 6; mi++) {
            const int r0 = mi * 16 + quad;
            float d[2][4];
            #pragma unroll
            for (int h = 0; h < 2; h++)
                #pragma unroll
                for (int q = 0; q < 4; q++) d[h][q] = 0.f;

            #pragma unroll
            for (int ks = 0; ks < 4; ks++) {
                const int ka = ks * 16 + 2 * t4;
                u32 a0 = ldb2(wh + r0 * 72 + ka);
                u32 a1 = ldb2(wh + (r0 + 8) * 72 + ka);
                u32 a2 = ldb2(wh + r0 * 72 + ka + 8);
                u32 a3 = ldb2(wh + (r0 + 8) * 72 + ka + 8);
                #pragma unroll
                for (int h = 0; h < 2; h++)
                    mma_bf16(d[h][0], d[h][1], d[h][2], d[h][3],
                             a0, a1, a2, a3, B[ks][h][0], B[ks][h][1]);
            }

            const int ra = r0, rb = r0 + 8;
            const float biasA = (ra < 48) ? ba[ra] : bb[ra - 48];
            const float biasB = (rb < 48) ? ba[rb] : bb[rb - 48];
            #pragma unroll
            for (int h = 0; h < 2; h++) {
                #pragma unroll
                for (int cc = 0; cc < 2; cc++) {
                    int col = nq * 16 + h * 8 + 2 * t4 + cc;
                    if (col < 250) {
                        int dt = col / 25, v = col - dt * 25;
                        {
                            float val = d[h][cc] + biasA;
                            if (ra < 48)
                                at[(ra >> 4) * K1_SBLK + v * K1_ATS + (ra & 15) * 10 + dt] =
                                    __float2bfloat16_rn(val);
                            else {
                                int r2 = ra - 48;
                                bt[(r2 >> 4) * K1_SBLK + v * K1_ATS + (r2 & 15) * 10 + dt] =
                                    __float2bfloat16_rn(val);
                            }
                        }
                        {
                            float val = d[h][2 + cc] + biasB;
                            if (rb < 48)
                                at[(rb >> 4) * K1_SBLK + v * K1_ATS + (rb & 15) * 10 + dt] =
                                    __float2bfloat16_rn(val);
                            else {
                                int r2 = rb - 48;
                                bt[(r2 >> 4) * K1_SBLK + v * K1_ATS + (r2 & 15) * 10 + dt] =
                                    __float2bfloat16_rn(val);
                            }
                        }
                    }
                }
            }
        }
    }
    __syncthreads();

    // Phase 2: scores via mma. 24 jobs (3 s x 2 v-tiles x 4 u-tiles), K=160.
    const float inv = 1.0f / 4800.0f;
    for (int job = wrp; job < 24; job += 16) {
        const int s = job >> 3, r = job & 7, mt = r >> 2, nt = r & 3;
        const int v0 = mt * 16 + quad;
        const int u0 = nt * 8 + quad;
        const __nv_bfloat16* as_ = at + s * K1_SBLK;
        const __nv_bfloat16* bs_ = bt + s * K1_SBLK;

        float d0 = 0.f, d1 = 0.f, d2 = 0.f, d3 = 0.f;
        #pragma unroll
        for (int ks = 0; ks < 10; ks++) {
            const int me = 2 * t4 + 16 * ks;
            u32 a0 = ldb2(as_ + v0 * K1_ATS + me);
            u32 a1 = ldb2(as_ + (v0 + 8) * K1_ATS + me);
            u32 a2 = ldb2(as_ + v0 * K1_ATS + me + 8);
            u32 a3 = ldb2(as_ + (v0 + 8) * K1_ATS + me + 8);
            u32 b0 = ldb2(bs_ + u0 * K1_ATS + me);
            u32 b1 = ldb2(bs_ + u0 * K1_ATS + me + 8);
            mma_bf16(d0, d1, d2, d3, a0, a1, a2, a3, b0, b1);
        }

        float* dst = g_part + (((size_t)ch * NB + n) * SS + s) * 625;
        const int uA = nt * 8 + 2 * t4, uB = uA + 1;
        const int vA = v0, vB = v0 + 8;
        if (vA < 25) {
            if (uA < 25) dst[vA * 25 + uA] = d0 * inv;
            if (uB < 25) dst[vA * 25 + uB] = d1 * inv;
        }
        if (vB < 25) {
            if (uA < 25) dst[vB * 25 + uA] = d2 * inv;
            if (uB < 25) dst[vB * 25 + uB] = d3 * inv;
        }
    }
}

// ============================================================================
// Kernel 2: reduce chunk partials, softmax over v, add A+PA -> g_att
// ============================================================================
__global__ void k2_softmax(const float* __restrict__ A, const float* __restrict__ PA)
{
    const int n = blockIdx.x, s = blockIdx.y;
    __shared__ float sc[625];
    const int tid = threadIdx.x;

    for (int i = tid; i < 625; i += 256) {
        float acc = 0.f;
        for (int ch = 0; ch < NCH1; ch++)
            acc += g_part[(((size_t)ch * NB + n) * SS + s) * 625 + i];
        sc[i] = acc;
    }
    __syncthreads();

    if (tid < 25) {
        const int u = tid;
        float mx = -1e30f;
        #pragma unroll
        for (int v = 0; v < 25; v++) mx = fmaxf(mx, sc[v * 25 + u]);
        float e[25], sum = 0.f;
        #pragma unroll
        for (int v = 0; v < 25; v++) { e[v] = expf(sc[v * 25 + u] - mx); sum += e[v]; }
        const float rs = 1.f / sum;
        #pragma unroll
        for (int v = 0; v < 25; v++) {
            int idx = s * 625 + v * 25 + u;
            g_att[((size_t)n * SS + s) * 625 + v * 25 + u] = e[v] * rs + A[idx] + PA[idx];
        }
    }
}

// ============================================================================
// Kernel 3: phase Y and phase Z on tensor cores. TC3=5, 512 thr, 2 CTAs/SM.
// (R10 version — measured ~280 us)
// ============================================================================
#define K3_OFF_XTH 0                      // [320][16w] bf16 = 5120 f
#define K3_OFF_XTL 5120
#define K3_OFF_ATH 10240                  // [3][32][16w] = 1536 f
#define K3_OFF_ATL 11776
#define K3_OFF_YH  13312                  // [128][72] bf16 = 4608 f
#define K3_OFF_YL  17920
#define K3_OFF_WH  22528                  // [64][72] bf16 = 2304 f
#define K3_OFF_WL  24832
#define K3_OFF_SC  27136
#define K3_OFF_SH  27200
#define K3_NF      27264
#define K3_SMEM    (K3_NF * 4)            // 109056 B

__global__ __launch_bounds__(512, 2)
void k3_fused(const float* __restrict__ x, const float* __restrict__ wd,
              const float* __restrict__ bd,
              const float* __restrict__ gma, const float* __restrict__ bta,
              const float* __restrict__ mu,  const float* __restrict__ var,
              float* __restrict__ out)
{
    const int n = blockIdx.x, ch = blockIdx.y, t0 = ch * TC3;
    const int tid = threadIdx.x, lane = tid & 31, wrp = tid >> 5;
    const int quad = lane >> 2, t4 = lane & 3;

    extern __shared__ float sm[];
    u32* xthw = (u32*)(sm + K3_OFF_XTH);   // [320][16 words] swizzled
    u32* xtlw = (u32*)(sm + K3_OFF_XTL);
    u32* athw = (u32*)(sm + K3_OFF_ATH);   // [3][32][16 words] swizzled
    u32* atlw = (u32*)(sm + K3_OFF_ATL);
    __nv_bfloat16* xth_b = (__nv_bfloat16*)(sm + K3_OFF_XTH);
    __nv_bfloat16* xtl_b = (__nv_bfloat16*)(sm + K3_OFF_XTL);
    __nv_bfloat16* y_hi = (__nv_bfloat16*)(sm + K3_OFF_YH);  // [128][72]
    __nv_bfloat16* y_lo = (__nv_bfloat16*)(sm + K3_OFF_YL);
    __nv_bfloat16* w_hi = (__nv_bfloat16*)(sm + K3_OFF_WH);  // [64][72]
    __nv_bfloat16* w_lo = (__nv_bfloat16*)(sm + K3_OFF_WL);
    float* sc_sm = sm + K3_OFF_SC;
    float* sh_sm = sm + K3_OFF_SH;

    // ---- stage x as hi/lo bf16 pairs, [m=(c*5+dt)][v], swizzled ------------
    const float* xg = x + (size_t)n * 64 * 7500 + (size_t)t0 * 25;
    for (int i = tid; i < 320 * 16; i += 512) {
        int m = i >> 4, w = i & 15;
        int c = m / 5, dt = m - 5 * c;
        int v0 = 2 * w;
        float f0 = (v0 < 25)     ? xg[(size_t)c * 7500 + dt * 25 + v0]     : 0.f;
        float f1 = (v0 + 1 < 25) ? xg[(size_t)c * 7500 + dt * 25 + v0 + 1] : 0.f;
        __nv_bfloat16 h0 = __float2bfloat16_rn(f0);
        __nv_bfloat16 h1 = __float2bfloat16_rn(f1);
        __nv_bfloat16 l0 = __float2bfloat16_rn(f0 - __bfloat162float(h0));
        __nv_bfloat16 l1 = __float2bfloat16_rn(f1 - __bfloat162float(h1));
        int a = idx16(m, w);
        xthw[a] = ((u32)*(unsigned short*)&h1 << 16) | *(unsigned short*)&h0;
        xtlw[a] = ((u32)*(unsigned short*)&l1 << 16) | *(unsigned short*)&l0;
    }
    // ---- stage att transposed [s][u][v], hi/lo, swizzled -------------------
    for (int i = tid; i < 3 * 512; i += 512) {
        int s = i >> 9, rem = i & 511;
        int u = rem >> 4, w = rem & 15;
        int v0 = 2 * w;
        const float* ag = g_att + ((size_t)n * SS + s) * 625;
        float f0 = (u < 25 && v0 < 25)     ? ag[v0 * 25 + u]       : 0.f;
        float f1 = (u < 25 && v0 + 1 < 25) ? ag[(v0 + 1) * 25 + u] : 0.f;
        __nv_bfloat16 h0 = __float2bfloat16_rn(f0);
        __nv_bfloat16 h1 = __float2bfloat16_rn(f1);
        __nv_bfloat16 l0 = __float2bfloat16_rn(f0 - __bfloat162float(h0));
        __nv_bfloat16 l1 = __float2bfloat16_rn(f1 - __bfloat162float(h1));
        int a = s * 512 + idx16(u, w);
        athw[a] = ((u32)*(unsigned short*)&h1 << 16) | *(unsigned short*)&h0;
        atlw[a] = ((u32)*(unsigned short*)&l1 << 16) | *(unsigned short*)&l0;
    }
    if (tid < 64) {
        float scl = gma[tid] * rsqrtf(var[tid] + 1e-5f);
        float bsum = bd[tid] + bd[64 + tid] + bd[128 + tid];
        sc_sm[tid] = scl;
        sh_sm[tid] = (bsum - mu[tid]) * scl + bta[tid];
    }
    if (tid < 3 * 72) {  // zero y rows j=125..127 (N-padding for phase Z)
        y_hi[125 * 72 + tid] = __float2bfloat16_rn(0.f);
        y_lo[125 * 72 + tid] = __float2bfloat16_rn(0.f);
    }

    // warp tiles: phase Y uses (mg, nt); phase Z uses (o0, jg)
    const int mg = wrp >> 2, nt = wrp & 3;
    const int o0 = mg * 16, jg = nt;
    float dz[4][4];
    #pragma unroll
    for (int f = 0; f < 4; f++)
        #pragma unroll
        for (int q = 0; q < 4; q++) dz[f][q] = 0.f;

    for (int s = 0; s < SS; s++) {
        __syncthreads();   // prev phase Z done with w/y; covers init on s=0

        // stage this subset's conv_d weights hi/lo (stride 72)
        for (int i = tid; i < 4096; i += 512) {
            int o = i >> 6, k = i & 63;
            float v = wd[(size_t)s * 4096 + i];
            __nv_bfloat16 h = __float2bfloat16_rn(v);
            w_hi[o * 72 + k] = h;
            w_lo[o * 72 + k] = __float2bfloat16_rn(v - __bfloat162float(h));
        }

        // ---- Phase Y (tensor cores): D[m][u] over K=v=32 -------------------
        {
            const int u = nt * 8 + quad;
            u32 bh[2][2], bl[2][2];
            #pragma unroll
            for (int ks = 0; ks < 2; ks++) {
                bh[ks][0] = athw[s * 512 + idx16(u, t4 + 8 * ks)];
                bh[ks][1] = athw[s * 512 + idx16(u, t4 + 4 + 8 * ks)];
                bl[ks][0] = atlw[s * 512 + idx16(u, t4 + 8 * ks)];
                bl[ks][1] = atlw[s * 512 + idx16(u, t4 + 4 + 8 * ks)];
            }
            #pragma unroll
            for (int q = 0; q < 5; q++) {
                const int mt = mg * 5 + q;
                const int m0 = mt * 16 + quad, m1 = m0 + 8;
                float D0 = 0.f, D1 = 0.f, D2 = 0.f, D3 = 0.f;
                #pragma unroll
                for (int ks = 0; ks < 2; ks++) {
                    u32 ah0 = xthw[idx16(m0, t4 + 8 * ks)];
                    u32 ah1 = xthw[idx16(m1, t4 + 8 * ks)];
                    u32 ah2 = xthw[idx16(m0, t4 + 4 + 8 * ks)];
                    u32 ah3 = xthw[idx16(m1, t4 + 4 + 8 * ks)];
                    u32 al0 = xtlw[idx16(m0, t4 + 8 * ks)];
                    u32 al1 = xtlw[idx16(m1, t4 + 8 * ks)];
                    u32 al2 = xtlw[idx16(m0, t4 + 4 + 8 * ks)];
                    u32 al3 = xtlw[idx16(m1, t4 + 4 + 8 * ks)];
                    mma_bf16(D0, D1, D2, D3, ah0, ah1, ah2, ah3, bh[ks][0], bh[ks][1]);
                    mma_bf16(D0, D1, D2, D3, ah0, ah1, ah2, ah3, bl[ks][0], bl[ks][1]);
                    mma_bf16(D0, D1, D2, D3, al0, al1, al2, al3, bh[ks][0], bh[ks][1]);
                }
                // scatter y hi/lo: (m, u) -> y[j = dt*25+u][c]
                const int u0 = nt * 8 + 2 * t4;
                #pragma unroll
                for (int cc = 0; cc < 2; cc++) {
                    int uu = u0 + cc;
                    if (uu < 25) {
                        {
                            int c = m0 / 5, dt = m0 - 5 * c;
                            int j = dt * 25 + uu;
                            float val = cc ? D1 : D0;
                            __nv_bfloat16 h = __float2bfloat16_rn(val);
                            y_hi[j * 72 + c] = h;
                            y_lo[j * 72 + c] = __float2bfloat16_rn(val - __bfloat162float(h));
                        }
                        {
                            int c = m1 / 5, dt = m1 - 5 * c;
                            int j = dt * 25 + uu;
                            float val = cc ? D3 : D2;
                            __nv_bfloat16 h = __float2bfloat16_rn(val);
                            y_hi[j * 72 + c] = h;
                            y_lo[j * 72 + c] = __float2bfloat16_rn(val - __bfloat162float(h));
                        }
                    }
                }
            }
        }
        __syncthreads();

        // ---- Phase Z (tensor cores): z += wd_s @ y_s, K=64 -----------------
        #pragma unroll
        for (int k0 = 0; k0 < 64; k0 += 16) {
            const int ar0 = (o0 + quad) * 72 + k0 + 2 * t4;
            const int ar1 = (o0 + quad + 8) * 72 + k0 + 2 * t4;
            u32 ah0 = ldb2(w_hi + ar0),     ah1 = ldb2(w_hi + ar1);
            u32 ah2 = ldb2(w_hi + ar0 + 8), ah3 = ldb2(w_hi + ar1 + 8);
            u32 al0 = ldb2(w_lo + ar0),     al1 = ldb2(w_lo + ar1);
            u32 al2 = ldb2(w_lo + ar0 + 8), al3 = ldb2(w_lo + ar1 + 8);
            #pragma unroll
            for (int f = 0; f < 4; f++) {
                int j = jg * 32 + f * 8 + quad;
                int br = j * 72 + k0 + 2 * t4;
                u32 bh0 = ldb2(y_hi + br), bh1 = ldb2(y_hi + br + 8);
                u32 bl0 = ldb2(y_lo + br), bl1 = ldb2(y_lo + br + 8);
                mma_bf16(dz[f][0], dz[f][1], dz[f][2], dz[f][3],
                         ah0, ah1, ah2, ah3, bh0, bh1);
                mma_bf16(dz[f][0], dz[f][1], dz[f][2], dz[f][3],
                         ah0, ah1, ah2, ah3, bl0, bl1);
                mma_bf16(dz[f][0], dz[f][1], dz[f][2], dz[f][3],
                         al0, al1, al2, al3, bh0, bh1);
            }
        }
    }

    // ---- epilogue: BN + residual (x = hi+lo) + ReLU ------------------------
    float* og = out + (size_t)n * 64 * 7500 + (size_t)t0 * 25;
    #pragma unroll
    for (int f = 0; f < 4; f++) {
        int jb = jg * 32 + f * 8 + 2 * t4;
        #pragma unroll
        for (int h = 0; h < 2; h++) {
            int o = o0 + quad + 8 * h;
            float scl = sc_sm[o], shf = sh_sm[o];
            #pragma unroll
            for (int cc = 0; cc < 2; cc++) {
                int j = jb + cc;
                if (j < 125) {
                    int dt = j / 25, u = j - dt * 25;
                    int r2 = o * 5 + dt;
                    int ew = 2 * idx16(r2, u >> 1) + (u & 1);
                    float xv = __bfloat162float(xth_b[ew]) + __bfloat162float(xtl_b[ew]);
                    float r = fmaf(dz[f][2 * h + cc], scl, shf) + xv;
                    og[(size_t)o * 7500 + j] = fmaxf(r, 0.f);
                }
            }
        }
    }
}

// ============================================================================
extern "C" void kernel_launch(void* const* d_in, const int* in_sizes, int n_in,
                              void* d_out, int out_size)
{
    const float* x   = (const float*)d_in[0];
    const float* A   = (const float*)d_in[1];
    const float* PA  = (const float*)d_in[2];
    const float* wa  = (const float*)d_in[3];
    const float* ba  = (const float*)d_in[4];
    const float* wb  = (const float*)d_in[5];
    const float* bb  = (const float*)d_in[6];
    const float* wd  = (const float*)d_in[7];
    const float* bd  = (const float*)d_in[8];
    const float* gma = (const float*)d_in[9];
    const float* bta = (const float*)d_in[10];
    const float* mu  = (const float*)d_in[11];
    const float* var = (const float*)d_in[12];
    float* out = (float*)d_out;

    cudaFuncSetAttribute(k1_scores, cudaFuncAttributeMaxDynamicSharedMemorySize, K1_SMEM);
    cudaFuncSetAttribute(k3_fused,  cudaFuncAttributeMaxDynamicSharedMemorySize, K3_SMEM);

    k1_scores<<<dim3(NB, NCH1), 512, K1_SMEM>>>(x, wa, ba, wb, bb);
    k2_softmax<<<dim3(NB, SS), 256>>>(A, PA);
    k3_fused<<<dim3(NB, NCH3), 512, K3_SMEM>>>(x, wd, bd, gma, bta, mu, var, out);
}